// round 5
// baseline (speedup 1.0000x reference)
#include <cuda_runtime.h>
#include <math.h>

#define B_   4
#define C_   256
#define H_   32
#define W_   32
#define N_   1024
#define NH_  8
#define HC_  32
#define NG_  4
#define GC_  64
#define BG_  16
#define SCALE_ 0.17677669529663687f   /* 32^-0.5 */
#define EPS_  1e-5f

// ---- scratch (device globals; no allocations allowed) ----
__device__ float g_q  [B_*C_*N_];
__device__ float g_pos[BG_*N_*2];
__device__ float g_xs [B_*C_*N_];
__device__ float g_k  [B_*C_*N_];
__device__ float g_v  [B_*C_*N_];
__device__ float g_o  [B_*C_*N_];

// ---- packed f32x2 helpers (FFMA2 is only reachable via PTX) ----
__device__ __forceinline__ void fma2(unsigned long long& d, unsigned long long a,
                                     unsigned long long b) {
    asm("fma.rn.f32x2 %0, %1, %2, %0;" : "+l"(d) : "l"(a), "l"(b));
}
__device__ __forceinline__ float2 u2f(unsigned long long v) {
    float2 r; asm("mov.b64 {%0, %1}, %2;" : "=f"(r.x), "=f"(r.y) : "l"(v)); return r;
}

// Fast exp on the FMA pipe (avoids MUFU throughput wall).
__device__ __forceinline__ float fexp(float x) {
    float t = fmaxf(x * 1.4426950408889634f, -126.0f);
    float n = rintf(t);
    float f = t - n;
    float p =             1.3333558146e-3f;
    p = fmaf(p, f, 9.6181291794e-3f);
    p = fmaf(p, f, 5.5504108625e-2f);
    p = fmaf(p, f, 2.4022650696e-1f);
    p = fmaf(p, f, 6.9314718056e-1f);
    p = fmaf(p, f, 1.0f);
    return p * __int_as_float(((int)n + 127) << 23);
}

// ============================================================
// GEMM tile body: Y[o,p] = sum_i W[o,i]*X[i,p] + bias[o]
// 64x64 tile, 256 threads, 4x4 per thread via FFMA2 pairs.
// W staged duplicated in smem so FFMA2 a-operand needs no packing.
// ============================================================
__device__ __forceinline__ void gemm_tile(
        const float* __restrict__ Wt, const float* __restrict__ bias,
        const float* __restrict__ Xb, float* __restrict__ Yb,
        int p0, int o0, float* Ws2, float* Xs) {
    int tid = threadIdx.x;
    int tx = tid & 15, ty = tid >> 4;
    int lc = tx << 2;
    unsigned long long acc[4][2] = {};

    for (int kt = 0; kt < C_; kt += 16) {
        float w0 = Wt[(size_t)(o0 + lc + 0) * C_ + kt + ty];
        float w1 = Wt[(size_t)(o0 + lc + 1) * C_ + kt + ty];
        float w2 = Wt[(size_t)(o0 + lc + 2) * C_ + kt + ty];
        float w3 = Wt[(size_t)(o0 + lc + 3) * C_ + kt + ty];
        *(float4*)&Ws2[ty * 132 + (lc << 1)]     = make_float4(w0, w0, w1, w1);
        *(float4*)&Ws2[ty * 132 + (lc << 1) + 4] = make_float4(w2, w2, w3, w3);
        *(float4*)&Xs[ty * 68 + lc] =
            *(const float4*)&Xb[(size_t)(kt + ty) * N_ + p0 + lc];
        __syncthreads();
#pragma unroll
        for (int kk = 0; kk < 16; kk++) {
            ulonglong2 wa = *(const ulonglong2*)&Ws2[kk * 132 + (ty << 3)];
            ulonglong2 xp = *(const ulonglong2*)&Xs[kk * 68 + (tx << 2)];
            fma2(acc[0][0], wa.x, xp.x); fma2(acc[0][1], wa.x, xp.y);
            fma2(acc[1][0], wa.y, xp.x); fma2(acc[1][1], wa.y, xp.y);
            ulonglong2 wb = *(const ulonglong2*)&Ws2[kk * 132 + (ty << 3) + 4];
            fma2(acc[2][0], wb.x, xp.x); fma2(acc[2][1], wb.x, xp.y);
            fma2(acc[3][0], wb.y, xp.x); fma2(acc[3][1], wb.y, xp.y);
        }
        __syncthreads();
    }
#pragma unroll
    for (int i = 0; i < 4; i++) {
        int o = o0 + (ty << 2) + i;
        float bs = bias[o];
        float2 lo = u2f(acc[i][0]), hi = u2f(acc[i][1]);
        *(float4*)&Yb[(size_t)o * N_ + p0 + lc] =
            make_float4(lo.x + bs, lo.y + bs, hi.x + bs, hi.y + bs);
    }
}

__global__ __launch_bounds__(256) void gemm_proj(
        const float* __restrict__ Wt, const float* __restrict__ bias,
        const float* __restrict__ X, float* __restrict__ Y) {
    __shared__ float Ws2[16 * 132];
    __shared__ float Xs[16 * 68];
    int b = blockIdx.z;
    gemm_tile(Wt, bias, X + (size_t)b * C_ * N_, Y + (size_t)b * C_ * N_,
              blockIdx.x << 6, blockIdx.y << 6, Ws2, Xs);
}

// K and V projections fused in one launch (same X).
__global__ __launch_bounds__(256) void gemm_kv(
        const float* __restrict__ Wk, const float* __restrict__ bk,
        const float* __restrict__ Wv, const float* __restrict__ bv,
        const float* __restrict__ X, float* __restrict__ Yk, float* __restrict__ Yv) {
    __shared__ float Ws2[16 * 132];
    __shared__ float Xs[16 * 68];
    int z = blockIdx.z;
    int b = z >> 1, sel = z & 1;
    const float* Wt = sel ? Wv : Wk;
    const float* bias = sel ? bv : bk;
    float* Y = sel ? Yv : Yk;
    gemm_tile(Wt, bias, X + (size_t)b * C_ * N_, Y + (size_t)b * C_ * N_,
              blockIdx.x << 6, blockIdx.y << 6, Ws2, Xs);
}

// ============================================================
// Offset network: depthwise 3x3 -> LN -> GELU -> pointwise(2)
// ============================================================
__global__ void offset_kernel(const float* __restrict__ dw_w, const float* __restrict__ dw_b,
                              const float* __restrict__ ln_w, const float* __restrict__ ln_b,
                              const float* __restrict__ pw_w) {
    int idx = blockIdx.x * blockDim.x + threadIdx.x;   // bg*N + p
    if (idx >= BG_ * N_) return;
    int bg = idx >> 10, p = idx & (N_ - 1);
    int h = p >> 5, w = p & 31;
    int b = bg >> 2, g = bg & 3;
    const float* qbase = g_q + (size_t)b * C_ * N_ + (size_t)g * GC_ * N_;

    float x[GC_];
    float s1 = 0.f;
#pragma unroll
    for (int c = 0; c < GC_; c++) {
        const float* qc = qbase + c * N_;
        float t = dw_b[c];
#pragma unroll
        for (int dy = 0; dy < 3; dy++) {
            int hh = h + dy - 1;
            if (hh < 0 || hh >= H_) continue;
#pragma unroll
            for (int dx = 0; dx < 3; dx++) {
                int ww = w + dx - 1;
                if (ww < 0 || ww >= W_) continue;
                t += dw_w[c * 9 + dy * 3 + dx] * qc[hh * W_ + ww];
            }
        }
        x[c] = t; s1 += t;
    }
    float mu = s1 * (1.f / GC_);
    float s2 = 0.f;
#pragma unroll
    for (int c = 0; c < GC_; c++) { float d = x[c] - mu; s2 += d * d; }
    float rinv = rsqrtf(s2 * (1.f / GC_) + EPS_);
    float off0 = 0.f, off1 = 0.f;
#pragma unroll
    for (int c = 0; c < GC_; c++) {
        float xn  = (x[c] - mu) * rinv * ln_w[c] + ln_b[c];
        float gel = 0.5f * xn * (1.f + erff(xn * 0.7071067811865476f));
        off0 += pw_w[c] * gel;          // y
        off1 += pw_w[GC_ + c] * gel;    // x
    }
    const float rng = 4.0f / 31.0f;
    float py = tanhf(off0) * rng + ((0.5f + (float)h) / 31.f) * 2.f - 1.f;
    float px = tanhf(off1) * rng + ((0.5f + (float)w) / 31.f) * 2.f - 1.f;
    g_pos[idx * 2 + 0] = py;
    g_pos[idx * 2 + 1] = px;
}

// ============================================================
// Deformable bilinear sampling of kv features
// ============================================================
__global__ void sample_kernel(const float* __restrict__ kv) {
    int blk = blockIdx.x;                 // bg*N + p
    int c = threadIdx.x;
    int bg = blk >> 10, p = blk & (N_ - 1);
    int b = bg >> 2, g = bg & 3;
    float py = g_pos[blk * 2 + 0], px = g_pos[blk * 2 + 1];
    float ix = (px + 1.f) * 15.5f;
    float iy = (py + 1.f) * 15.5f;
    float x0f = floorf(ix), y0f = floorf(iy);
    float wx1 = ix - x0f, wx0 = 1.f - wx1;
    float wy1 = iy - y0f, wy0 = 1.f - wy1;
    int x0 = (int)x0f, y0 = (int)y0f;
    const float* src = kv + ((size_t)b * C_ + g * GC_ + c) * N_;
    float acc = 0.f;
#pragma unroll
    for (int cy = 0; cy < 2; cy++) {
        int yy = y0 + cy;
        if (yy < 0 || yy >= H_) continue;
        float wy = cy ? wy1 : wy0;
#pragma unroll
        for (int cx = 0; cx < 2; cx++) {
            int xx = x0 + cx;
            if (xx < 0 || xx >= W_) continue;
            acc += wy * (cx ? wx1 : wx0) * src[yy * W_ + xx];
        }
    }
    g_xs[((size_t)b * C_ + g * GC_ + c) * N_ + p] = acc;
}

// ============================================================
// Fused flash attention (FFMA2 everywhere, max-free softmax,
// zero-padded smem RPE table with constant-fraction bilinear).
// ============================================================
#define FL_QS2 0
#define FL_KS  16896
#define FL_VS  25600
#define FL_PS  34304
#define FL_TB  51712
#define FL_PY  70480
#define FL_PX  70736
#define FL_SMEM 70992

__global__ __launch_bounds__(256) void flash_kernel(const float* __restrict__ rpe) {
    extern __shared__ char sm_[];
    float* qs2 = (float*)(sm_ + FL_QS2);   // [32][132] dup q pairs
    float* ks  = (float*)(sm_ + FL_KS);    // [32][68]
    float* vs  = (float*)(sm_ + FL_VS);    // [32][68]
    float* ps  = (float*)(sm_ + FL_PS);    // [64][68]
    float* tb  = (float*)(sm_ + FL_TB);    // [68][69] zero-padded rpe table
    float* pyn = (float*)(sm_ + FL_PY);    // 64
    float* pxn = (float*)(sm_ + FL_PX);    // 64

    int tid = threadIdx.x;
    int tx = tid & 15, ty = tid >> 4;
    int bh = blockIdx.y, b = bh >> 3, hd = bh & 7;
    int m0 = blockIdx.x << 6;

    const float* qb = g_q + (size_t)(b * C_ + hd * HC_) * N_;
    const float* kb = g_k + (size_t)(b * C_ + hd * HC_) * N_;
    const float* vb = g_v + (size_t)(b * C_ + hd * HC_) * N_;
    int bg = b * NG_ + (hd >> 1);
    const float* tsrc = rpe + hd * 3969;

    // zero the padded table
    for (int i = tid; i < 68 * 69; i += 256) tb[i] = 0.f;
    // q tile, duplicated pairs, pre-scaled
    for (int i = tid; i < 512; i += 256) {
        int c = i >> 4, mg = (i & 15) << 2;
        float4 v = *(const float4*)&qb[(size_t)c * N_ + m0 + mg];
        v.x *= SCALE_; v.y *= SCALE_; v.z *= SCALE_; v.w *= SCALE_;
        float* d = &qs2[c * 132 + (mg << 1)];
        ((float4*)d)[0] = make_float4(v.x, v.x, v.y, v.y);
        ((float4*)d)[1] = make_float4(v.z, v.z, v.w, v.w);
    }
    __syncthreads();
    // fill table interior at [2][2]
    for (int i = tid; i < 3969; i += 256) {
        int y = i / 63, x = i - y * 63;
        tb[(y + 2) * 69 + x + 2] = tsrc[i];
    }

    int moff[4];
#pragma unroll
    for (int i = 0; i < 4; i++) {
        int m = m0 + (ty << 2) + i;
        moff[i] = (m >> 5) * 69 + (m & 31);
    }

    unsigned long long o20[4] = {}, o21[4] = {};
    float rsum[4] = {};

    for (int nt = 0; nt < 16; nt++) {
        int n0 = nt << 6;
        __syncthreads();   // prev PV done (and, on iter 0, table fill done)
        for (int i = tid; i < 512; i += 256) {
            int c = i >> 4, col = (i & 15) << 2;
            *(float4*)&ks[c * 68 + col] = *(const float4*)&kb[(size_t)c * N_ + n0 + col];
            *(float4*)&vs[c * 68 + col] = *(const float4*)&vb[(size_t)c * N_ + n0 + col];
        }
        if (tid < 64) {
            pyn[tid] = 15.5f - 15.5f * g_pos[((size_t)bg * N_ + n0 + tid) * 2 + 0];
            pxn[tid] = 15.5f - 15.5f * g_pos[((size_t)bg * N_ + n0 + tid) * 2 + 1];
        }
        __syncthreads();

        // ---- S = (scaled Q)^T K via FFMA2 ----
        unsigned long long s2[4][2] = {};
#pragma unroll
        for (int c = 0; c < 32; c++) {
            ulonglong2 qa = *(const ulonglong2*)&qs2[c * 132 + (ty << 3)];
            ulonglong2 kp = *(const ulonglong2*)&ks[c * 68 + (tx << 2)];
            fma2(s2[0][0], qa.x, kp.x); fma2(s2[0][1], qa.x, kp.y);
            fma2(s2[1][0], qa.y, kp.x); fma2(s2[1][1], qa.y, kp.y);
            ulonglong2 qc = *(const ulonglong2*)&qs2[c * 132 + (ty << 3) + 4];
            fma2(s2[2][0], qc.x, kp.x); fma2(s2[2][1], qc.x, kp.y);
            fma2(s2[3][0], qc.y, kp.x); fma2(s2[3][1], qc.y, kp.y);
        }
        float sv[4][4];
#pragma unroll
        for (int i = 0; i < 4; i++) {
            float2 a = u2f(s2[i][0]); float2 c2 = u2f(s2[i][1]);
            sv[i][0] = a.x; sv[i][1] = a.y; sv[i][2] = c2.x; sv[i][3] = c2.y;
        }

        // ---- + rpe bias (fractions constant per n; zero-padded table) ----
#pragma unroll
        for (int j = 0; j < 4; j++) {
            int nn = (tx << 2) + j;
            float biy = pyn[nn], bix = pxn[nn];
            float fy = floorf(biy), fx = floorf(bix);
            float wy1 = biy - fy, wx1 = bix - fx;
            float wy0 = 1.f - wy1, wx0 = 1.f - wx1;
            int idxb = ((int)fy + 2) * 69 + (int)fx + 2;
            float w00 = wy0 * wx0, w01 = wy0 * wx1;
            float w10 = wy1 * wx0, w11 = wy1 * wx1;
#pragma unroll
            for (int i = 0; i < 4; i++) {
                int idx = idxb + moff[i];
                float bsum = w00 * tb[idx] + w01 * tb[idx + 1]
                           + w10 * tb[idx + 69] + w11 * tb[idx + 70];
                sv[i][j] += bsum;
            }
        }

        // ---- exp (no max subtraction; scores are O(1)) ----
#pragma unroll
        for (int i = 0; i < 4; i++) {
            float p0 = fexp(sv[i][0]);
            float p1 = fexp(sv[i][1]);
            float p2 = fexp(sv[i][2]);
            float p3 = fexp(sv[i][3]);
            rsum[i] += (p0 + p1) + (p2 + p3);
            *(float4*)&ps[((ty << 2) + i) * 68 + (tx << 2)] = make_float4(p0, p1, p2, p3);
        }
        __syncwarp();

        // ---- O += P * V via FFMA2 (pairwise over n, horizontal add at end) ----
#pragma unroll
        for (int n4 = 0; n4 < 16; n4++) {
            ulonglong2 v0 = *(const ulonglong2*)&vs[tx * 68 + (n4 << 2)];
            ulonglong2 v1 = *(const ulonglong2*)&vs[(tx + 16) * 68 + (n4 << 2)];
#pragma unroll
            for (int i = 0; i < 4; i++) {
                ulonglong2 pp = *(const ulonglong2*)&ps[((ty << 2) + i) * 68 + (n4 << 2)];
                fma2(o20[i], pp.x, v0.x); fma2(o20[i], pp.y, v0.y);
                fma2(o21[i], pp.x, v1.x); fma2(o21[i], pp.y, v1.y);
            }
        }
    }

    // final sum reduction (once, not per tile) and normalize
    float inv[4];
#pragma unroll
    for (int i = 0; i < 4; i++) {
        float rs = rsum[i];
#pragma unroll
        for (int off = 1; off < 16; off <<= 1)
            rs += __shfl_xor_sync(0xffffffffu, rs, off);
        inv[i] = 1.f / rs;
    }
    __syncthreads();
#pragma unroll
    for (int i = 0; i < 4; i++) {
        float2 a = u2f(o20[i]); float2 c2 = u2f(o21[i]);
        ps[((ty << 2) + i) * 68 + tx]      = (a.x + a.y) * inv[i];
        ps[((ty << 2) + i) * 68 + tx + 16] = (c2.x + c2.y) * inv[i];
    }
    __syncthreads();
    float* ob = g_o + (size_t)(b * C_ + hd * HC_) * N_;
    for (int i = tid; i < 2048; i += 256) {
        int c = i >> 6, m = i & 63;
        ob[(size_t)c * N_ + m0 + m] = ps[m * 68 + c];
    }
}

// ============================================================
extern "C" void kernel_launch(void* const* d_in, const int* in_sizes, int n_in,
                              void* d_out, int out_size) {
    const float* q_feat = (const float*)d_in[0];
    const float* kv_feat = (const float*)d_in[1];
    const float* Wq = (const float*)d_in[2];
    const float* bq = (const float*)d_in[3];
    const float* Wk = (const float*)d_in[4];
    const float* bk = (const float*)d_in[5];
    const float* Wv = (const float*)d_in[6];
    const float* bv = (const float*)d_in[7];
    const float* Wo = (const float*)d_in[8];
    const float* bo = (const float*)d_in[9];
    const float* dw_w = (const float*)d_in[10];
    const float* dw_b = (const float*)d_in[11];
    const float* ln_w = (const float*)d_in[12];
    const float* ln_b = (const float*)d_in[13];
    const float* pw_w = (const float*)d_in[14];
    const float* rpe  = (const float*)d_in[15];
    float* out = (float*)d_out;

    float *gq, *gxs, *gk, *gv, *go;
    cudaGetSymbolAddress((void**)&gq,  g_q);
    cudaGetSymbolAddress((void**)&gxs, g_xs);
    cudaGetSymbolAddress((void**)&gk,  g_k);
    cudaGetSymbolAddress((void**)&gv,  g_v);
    cudaGetSymbolAddress((void**)&go,  g_o);

    static int smem_set = 0;
    if (!smem_set) {
        cudaFuncSetAttribute(flash_kernel,
                             cudaFuncAttributeMaxDynamicSharedMemorySize, FL_SMEM);
        smem_set = 1;
    }

    dim3 gemm_grid(N_ / 64, C_ / 64, B_);
    dim3 kv_grid(N_ / 64, C_ / 64, B_ * 2);

    // 1. q projection
    gemm_proj<<<gemm_grid, 256>>>(Wq, bq, q_feat, gq);
    // 2. offset network -> pos
    offset_kernel<<<(BG_ * N_ + 255) / 256, 256>>>(dw_w, dw_b, ln_w, ln_b, pw_w);
    // 3. deformable sampling of kv
    sample_kernel<<<BG_ * N_, GC_>>>(kv_feat);
    // 4. k + v projections (fused launch)
    gemm_kv<<<kv_grid, 256>>>(Wk, bk, Wv, bv, gxs, gk, gv);
    // 5-7. fused scores + bias + softmax + AV
    flash_kernel<<<dim3(N_ / 64, B_ * NH_), 256, FL_SMEM>>>(rpe);
    // 8. output projection
    gemm_proj<<<gemm_grid, 256>>>(Wo, bo, go, out);
}

// round 6
// speedup vs baseline: 1.0041x; 1.0041x over previous
#include <cuda_runtime.h>
#include <math.h>

#define B_   4
#define C_   256
#define H_   32
#define W_   32
#define N_   1024
#define NH_  8
#define HC_  32
#define NG_  4
#define GC_  64
#define BG_  16
#define SCALE_ 0.17677669529663687f   /* 32^-0.5 */
#define EPS_  1e-5f

// ---- scratch (device globals; no allocations allowed) ----
__device__ float g_q  [B_*C_*N_];
__device__ float g_pos[BG_*N_*2];
__device__ float g_xs [B_*C_*N_];
__device__ float g_k  [B_*C_*N_];
__device__ float g_v  [B_*C_*N_];
__device__ float g_o  [B_*C_*N_];

// ---- packed f32x2 helpers (FFMA2 is only reachable via PTX) ----
__device__ __forceinline__ void fma2(unsigned long long& d, unsigned long long a,
                                     unsigned long long b) {
    asm("fma.rn.f32x2 %0, %1, %2, %0;" : "+l"(d) : "l"(a), "l"(b));
}
__device__ __forceinline__ float2 u2f(unsigned long long v) {
    float2 r; asm("mov.b64 {%0, %1}, %2;" : "=f"(r.x), "=f"(r.y) : "l"(v)); return r;
}

// Fast exp on the FMA pipe (avoids MUFU throughput wall).
__device__ __forceinline__ float fexp(float x) {
    float t = fmaxf(x * 1.4426950408889634f, -126.0f);
    float n = rintf(t);
    float f = t - n;
    float p =             1.3333558146e-3f;
    p = fmaf(p, f, 9.6181291794e-3f);
    p = fmaf(p, f, 5.5504108625e-2f);
    p = fmaf(p, f, 2.4022650696e-1f);
    p = fmaf(p, f, 6.9314718056e-1f);
    p = fmaf(p, f, 1.0f);
    return p * __int_as_float(((int)n + 127) << 23);
}

// ============================================================
// GEMM tile body: Y[o,p] = sum_i W[o,i]*X[i,p] + bias[o]
// 64x64 tile, 256 threads, 4x4 per thread via FFMA2 pairs.
// W staged duplicated in smem so FFMA2 a-operand needs no packing.
// ============================================================
__device__ __forceinline__ void gemm_tile(
        const float* __restrict__ Wt, const float* __restrict__ bias,
        const float* __restrict__ Xb, float* __restrict__ Yb,
        int p0, int o0, float* Ws2, float* Xs) {
    int tid = threadIdx.x;
    int tx = tid & 15, ty = tid >> 4;
    int lc = tx << 2;
    unsigned long long acc[4][2] = {};

    for (int kt = 0; kt < C_; kt += 16) {
        float w0 = Wt[(size_t)(o0 + lc + 0) * C_ + kt + ty];
        float w1 = Wt[(size_t)(o0 + lc + 1) * C_ + kt + ty];
        float w2 = Wt[(size_t)(o0 + lc + 2) * C_ + kt + ty];
        float w3 = Wt[(size_t)(o0 + lc + 3) * C_ + kt + ty];
        *(float4*)&Ws2[ty * 132 + (lc << 1)]     = make_float4(w0, w0, w1, w1);
        *(float4*)&Ws2[ty * 132 + (lc << 1) + 4] = make_float4(w2, w2, w3, w3);
        *(float4*)&Xs[ty * 68 + lc] =
            *(const float4*)&Xb[(size_t)(kt + ty) * N_ + p0 + lc];
        __syncthreads();
#pragma unroll
        for (int kk = 0; kk < 16; kk++) {
            ulonglong2 wa = *(const ulonglong2*)&Ws2[kk * 132 + (ty << 3)];
            ulonglong2 xp = *(const ulonglong2*)&Xs[kk * 68 + (tx << 2)];
            fma2(acc[0][0], wa.x, xp.x); fma2(acc[0][1], wa.x, xp.y);
            fma2(acc[1][0], wa.y, xp.x); fma2(acc[1][1], wa.y, xp.y);
            ulonglong2 wb = *(const ulonglong2*)&Ws2[kk * 132 + (ty << 3) + 4];
            fma2(acc[2][0], wb.x, xp.x); fma2(acc[2][1], wb.x, xp.y);
            fma2(acc[3][0], wb.y, xp.x); fma2(acc[3][1], wb.y, xp.y);
        }
        __syncthreads();
    }
#pragma unroll
    for (int i = 0; i < 4; i++) {
        int o = o0 + (ty << 2) + i;
        float bs = bias[o];
        float2 lo = u2f(acc[i][0]), hi = u2f(acc[i][1]);
        *(float4*)&Yb[(size_t)o * N_ + p0 + lc] =
            make_float4(lo.x + bs, lo.y + bs, hi.x + bs, hi.y + bs);
    }
}

__global__ __launch_bounds__(256) void gemm_proj(
        const float* __restrict__ Wt, const float* __restrict__ bias,
        const float* __restrict__ X, float* __restrict__ Y) {
    __shared__ float Ws2[16 * 132];
    __shared__ float Xs[16 * 68];
    int b = blockIdx.z;
    gemm_tile(Wt, bias, X + (size_t)b * C_ * N_, Y + (size_t)b * C_ * N_,
              blockIdx.x << 6, blockIdx.y << 6, Ws2, Xs);
}

// K and V projections fused in one launch (same X).
__global__ __launch_bounds__(256) void gemm_kv(
        const float* __restrict__ Wk, const float* __restrict__ bk,
        const float* __restrict__ Wv, const float* __restrict__ bv,
        const float* __restrict__ X, float* __restrict__ Yk, float* __restrict__ Yv) {
    __shared__ float Ws2[16 * 132];
    __shared__ float Xs[16 * 68];
    int z = blockIdx.z;
    int b = z >> 1, sel = z & 1;
    const float* Wt = sel ? Wv : Wk;
    const float* bias = sel ? bv : bk;
    float* Y = sel ? Yv : Yk;
    gemm_tile(Wt, bias, X + (size_t)b * C_ * N_, Y + (size_t)b * C_ * N_,
              blockIdx.x << 6, blockIdx.y << 6, Ws2, Xs);
}

// ============================================================
// Offset network: depthwise 3x3 -> LN -> GELU -> pointwise(2)
// ============================================================
__global__ void offset_kernel(const float* __restrict__ dw_w, const float* __restrict__ dw_b,
                              const float* __restrict__ ln_w, const float* __restrict__ ln_b,
                              const float* __restrict__ pw_w) {
    int idx = blockIdx.x * blockDim.x + threadIdx.x;   // bg*N + p
    if (idx >= BG_ * N_) return;
    int bg = idx >> 10, p = idx & (N_ - 1);
    int h = p >> 5, w = p & 31;
    int b = bg >> 2, g = bg & 3;
    const float* qbase = g_q + (size_t)b * C_ * N_ + (size_t)g * GC_ * N_;

    float x[GC_];
    float s1 = 0.f;
#pragma unroll
    for (int c = 0; c < GC_; c++) {
        const float* qc = qbase + c * N_;
        float t = dw_b[c];
#pragma unroll
        for (int dy = 0; dy < 3; dy++) {
            int hh = h + dy - 1;
            if (hh < 0 || hh >= H_) continue;
#pragma unroll
            for (int dx = 0; dx < 3; dx++) {
                int ww = w + dx - 1;
                if (ww < 0 || ww >= W_) continue;
                t += dw_w[c * 9 + dy * 3 + dx] * qc[hh * W_ + ww];
            }
        }
        x[c] = t; s1 += t;
    }
    float mu = s1 * (1.f / GC_);
    float s2 = 0.f;
#pragma unroll
    for (int c = 0; c < GC_; c++) { float d = x[c] - mu; s2 += d * d; }
    float rinv = rsqrtf(s2 * (1.f / GC_) + EPS_);
    float off0 = 0.f, off1 = 0.f;
#pragma unroll
    for (int c = 0; c < GC_; c++) {
        float xn  = (x[c] - mu) * rinv * ln_w[c] + ln_b[c];
        float gel = 0.5f * xn * (1.f + erff(xn * 0.7071067811865476f));
        off0 += pw_w[c] * gel;          // y
        off1 += pw_w[GC_ + c] * gel;    // x
    }
    const float rng = 4.0f / 31.0f;
    float py = tanhf(off0) * rng + ((0.5f + (float)h) / 31.f) * 2.f - 1.f;
    float px = tanhf(off1) * rng + ((0.5f + (float)w) / 31.f) * 2.f - 1.f;
    g_pos[idx * 2 + 0] = py;
    g_pos[idx * 2 + 1] = px;
}

// ============================================================
// Deformable bilinear sampling of kv features
// ============================================================
__global__ void sample_kernel(const float* __restrict__ kv) {
    int blk = blockIdx.x;                 // bg*N + p
    int c = threadIdx.x;
    int bg = blk >> 10, p = blk & (N_ - 1);
    int b = bg >> 2, g = bg & 3;
    float py = g_pos[blk * 2 + 0], px = g_pos[blk * 2 + 1];
    float ix = (px + 1.f) * 15.5f;
    float iy = (py + 1.f) * 15.5f;
    float x0f = floorf(ix), y0f = floorf(iy);
    float wx1 = ix - x0f, wx0 = 1.f - wx1;
    float wy1 = iy - y0f, wy0 = 1.f - wy1;
    int x0 = (int)x0f, y0 = (int)y0f;
    const float* src = kv + ((size_t)b * C_ + g * GC_ + c) * N_;
    float acc = 0.f;
#pragma unroll
    for (int cy = 0; cy < 2; cy++) {
        int yy = y0 + cy;
        if (yy < 0 || yy >= H_) continue;
        float wy = cy ? wy1 : wy0;
#pragma unroll
        for (int cx = 0; cx < 2; cx++) {
            int xx = x0 + cx;
            if (xx < 0 || xx >= W_) continue;
            acc += wy * (cx ? wx1 : wx0) * src[yy * W_ + xx];
        }
    }
    g_xs[((size_t)b * C_ + g * GC_ + c) * N_ + p] = acc;
}

// ============================================================
// Fused flash attention (FFMA2 everywhere, max-free softmax,
// zero-padded smem RPE table with constant-fraction bilinear).
// ============================================================
#define FL_QS2 0
#define FL_KS  16896
#define FL_VS  25600
#define FL_PS  34304
#define FL_TB  51712
#define FL_PY  70480
#define FL_PX  70736
#define FL_SMEM 70992

__global__ __launch_bounds__(256) void flash_kernel(const float* __restrict__ rpe) {
    extern __shared__ char sm_[];
    float* qs2 = (float*)(sm_ + FL_QS2);   // [32][132] dup q pairs
    float* ks  = (float*)(sm_ + FL_KS);    // [32][68]
    float* vs  = (float*)(sm_ + FL_VS);    // [32][68]
    float* ps  = (float*)(sm_ + FL_PS);    // [64][68]
    float* tb  = (float*)(sm_ + FL_TB);    // [68][69] zero-padded rpe table
    float* pyn = (float*)(sm_ + FL_PY);    // 64
    float* pxn = (float*)(sm_ + FL_PX);    // 64

    int tid = threadIdx.x;
    int tx = tid & 15, ty = tid >> 4;
    int bh = blockIdx.y, b = bh >> 3, hd = bh & 7;
    int m0 = blockIdx.x << 6;

    const float* qb = g_q + (size_t)(b * C_ + hd * HC_) * N_;
    const float* kb = g_k + (size_t)(b * C_ + hd * HC_) * N_;
    const float* vb = g_v + (size_t)(b * C_ + hd * HC_) * N_;
    int bg = b * NG_ + (hd >> 1);
    const float* tsrc = rpe + hd * 3969;

    // zero the padded table
    for (int i = tid; i < 68 * 69; i += 256) tb[i] = 0.f;
    // q tile, duplicated pairs, pre-scaled
    for (int i = tid; i < 512; i += 256) {
        int c = i >> 4, mg = (i & 15) << 2;
        float4 v = *(const float4*)&qb[(size_t)c * N_ + m0 + mg];
        v.x *= SCALE_; v.y *= SCALE_; v.z *= SCALE_; v.w *= SCALE_;
        float* d = &qs2[c * 132 + (mg << 1)];
        ((float4*)d)[0] = make_float4(v.x, v.x, v.y, v.y);
        ((float4*)d)[1] = make_float4(v.z, v.z, v.w, v.w);
    }
    __syncthreads();
    // fill table interior at [2][2]
    for (int i = tid; i < 3969; i += 256) {
        int y = i / 63, x = i - y * 63;
        tb[(y + 2) * 69 + x + 2] = tsrc[i];
    }

    int moff[4];
#pragma unroll
    for (int i = 0; i < 4; i++) {
        int m = m0 + (ty << 2) + i;
        moff[i] = (m >> 5) * 69 + (m & 31);
    }

    unsigned long long o20[4] = {}, o21[4] = {};
    float rsum[4] = {};

    for (int nt = 0; nt < 16; nt++) {
        int n0 = nt << 6;
        __syncthreads();   // prev PV done (and, on iter 0, table fill done)
        for (int i = tid; i < 512; i += 256) {
            int c = i >> 4, col = (i & 15) << 2;
            *(float4*)&ks[c * 68 + col] = *(const float4*)&kb[(size_t)c * N_ + n0 + col];
            *(float4*)&vs[c * 68 + col] = *(const float4*)&vb[(size_t)c * N_ + n0 + col];
        }
        if (tid < 64) {
            pyn[tid] = 15.5f - 15.5f * g_pos[((size_t)bg * N_ + n0 + tid) * 2 + 0];
            pxn[tid] = 15.5f - 15.5f * g_pos[((size_t)bg * N_ + n0 + tid) * 2 + 1];
        }
        __syncthreads();

        // ---- S = (scaled Q)^T K via FFMA2 ----
        unsigned long long s2[4][2] = {};
#pragma unroll
        for (int c = 0; c < 32; c++) {
            ulonglong2 qa = *(const ulonglong2*)&qs2[c * 132 + (ty << 3)];
            ulonglong2 kp = *(const ulonglong2*)&ks[c * 68 + (tx << 2)];
            fma2(s2[0][0], qa.x, kp.x); fma2(s2[0][1], qa.x, kp.y);
            fma2(s2[1][0], qa.y, kp.x); fma2(s2[1][1], qa.y, kp.y);
            ulonglong2 qc = *(const ulonglong2*)&qs2[c * 132 + (ty << 3) + 4];
            fma2(s2[2][0], qc.x, kp.x); fma2(s2[2][1], qc.x, kp.y);
            fma2(s2[3][0], qc.y, kp.x); fma2(s2[3][1], qc.y, kp.y);
        }
        float sv[4][4];
#pragma unroll
        for (int i = 0; i < 4; i++) {
            float2 a = u2f(s2[i][0]); float2 c2 = u2f(s2[i][1]);
            sv[i][0] = a.x; sv[i][1] = a.y; sv[i][2] = c2.x; sv[i][3] = c2.y;
        }

        // ---- + rpe bias (fractions constant per n; zero-padded table) ----
#pragma unroll
        for (int j = 0; j < 4; j++) {
            int nn = (tx << 2) + j;
            float biy = pyn[nn], bix = pxn[nn];
            float fy = floorf(biy), fx = floorf(bix);
            float wy1 = biy - fy, wx1 = bix - fx;
            float wy0 = 1.f - wy1, wx0 = 1.f - wx1;
            int idxb = ((int)fy + 2) * 69 + (int)fx + 2;
            float w00 = wy0 * wx0, w01 = wy0 * wx1;
            float w10 = wy1 * wx0, w11 = wy1 * wx1;
#pragma unroll
            for (int i = 0; i < 4; i++) {
                int idx = idxb + moff[i];
                float bsum = w00 * tb[idx] + w01 * tb[idx + 1]
                           + w10 * tb[idx + 69] + w11 * tb[idx + 70];
                sv[i][j] += bsum;
            }
        }

        // ---- exp (no max subtraction; scores are O(1)) ----
#pragma unroll
        for (int i = 0; i < 4; i++) {
            float p0 = fexp(sv[i][0]);
            float p1 = fexp(sv[i][1]);
            float p2 = fexp(sv[i][2]);
            float p3 = fexp(sv[i][3]);
            rsum[i] += (p0 + p1) + (p2 + p3);
            *(float4*)&ps[((ty << 2) + i) * 68 + (tx << 2)] = make_float4(p0, p1, p2, p3);
        }
        __syncwarp();

        // ---- O += P * V via FFMA2 (pairwise over n, horizontal add at end) ----
#pragma unroll
        for (int n4 = 0; n4 < 16; n4++) {
            ulonglong2 v0 = *(const ulonglong2*)&vs[tx * 68 + (n4 << 2)];
            ulonglong2 v1 = *(const ulonglong2*)&vs[(tx + 16) * 68 + (n4 << 2)];
#pragma unroll
            for (int i = 0; i < 4; i++) {
                ulonglong2 pp = *(const ulonglong2*)&ps[((ty << 2) + i) * 68 + (n4 << 2)];
                fma2(o20[i], pp.x, v0.x); fma2(o20[i], pp.y, v0.y);
                fma2(o21[i], pp.x, v1.x); fma2(o21[i], pp.y, v1.y);
            }
        }
    }

    // final sum reduction (once, not per tile) and normalize
    float inv[4];
#pragma unroll
    for (int i = 0; i < 4; i++) {
        float rs = rsum[i];
#pragma unroll
        for (int off = 1; off < 16; off <<= 1)
            rs += __shfl_xor_sync(0xffffffffu, rs, off);
        inv[i] = 1.f / rs;
    }
    __syncthreads();
#pragma unroll
    for (int i = 0; i < 4; i++) {
        float2 a = u2f(o20[i]); float2 c2 = u2f(o21[i]);
        ps[((ty << 2) + i) * 68 + tx]      = (a.x + a.y) * inv[i];
        ps[((ty << 2) + i) * 68 + tx + 16] = (c2.x + c2.y) * inv[i];
    }
    __syncthreads();
    float* ob = g_o + (size_t)(b * C_ + hd * HC_) * N_;
    for (int i = tid; i < 2048; i += 256) {
        int c = i >> 6, m = i & 63;
        ob[(size_t)c * N_ + m0 + m] = ps[m * 68 + c];
    }
}

// ============================================================
extern "C" void kernel_launch(void* const* d_in, const int* in_sizes, int n_in,
                              void* d_out, int out_size) {
    const float* q_feat = (const float*)d_in[0];
    const float* kv_feat = (const float*)d_in[1];
    const float* Wq = (const float*)d_in[2];
    const float* bq = (const float*)d_in[3];
    const float* Wk = (const float*)d_in[4];
    const float* bk = (const float*)d_in[5];
    const float* Wv = (const float*)d_in[6];
    const float* bv = (const float*)d_in[7];
    const float* Wo = (const float*)d_in[8];
    const float* bo = (const float*)d_in[9];
    const float* dw_w = (const float*)d_in[10];
    const float* dw_b = (const float*)d_in[11];
    const float* ln_w = (const float*)d_in[12];
    const float* ln_b = (const float*)d_in[13];
    const float* pw_w = (const float*)d_in[14];
    const float* rpe  = (const float*)d_in[15];
    float* out = (float*)d_out;

    float *gq, *gxs, *gk, *gv, *go;
    cudaGetSymbolAddress((void**)&gq,  g_q);
    cudaGetSymbolAddress((void**)&gxs, g_xs);
    cudaGetSymbolAddress((void**)&gk,  g_k);
    cudaGetSymbolAddress((void**)&gv,  g_v);
    cudaGetSymbolAddress((void**)&go,  g_o);

    static int smem_set = 0;
    if (!smem_set) {
        cudaFuncSetAttribute(flash_kernel,
                             cudaFuncAttributeMaxDynamicSharedMemorySize, FL_SMEM);
        smem_set = 1;
    }

    dim3 gemm_grid(N_ / 64, C_ / 64, B_);
    dim3 kv_grid(N_ / 64, C_ / 64, B_ * 2);

    // 1. q projection
    gemm_proj<<<gemm_grid, 256>>>(Wq, bq, q_feat, gq);
    // 2. offset network -> pos
    offset_kernel<<<(BG_ * N_ + 255) / 256, 256>>>(dw_w, dw_b, ln_w, ln_b, pw_w);
    // 3. deformable sampling of kv
    sample_kernel<<<BG_ * N_, GC_>>>(kv_feat);
    // 4. k + v projections (fused launch)
    gemm_kv<<<kv_grid, 256>>>(Wk, bk, Wv, bv, gxs, gk, gv);
    // 5-7. fused scores + bias + softmax + AV
    flash_kernel<<<dim3(N_ / 64, B_ * NH_), 256, FL_SMEM>>>(rpe);
    // 8. output projection
    gemm_proj<<<gemm_grid, 256>>>(Wo, bo, go, out);
}

// round 7
// speedup vs baseline: 1.2074x; 1.2024x over previous
#include <cuda_runtime.h>
#include <math.h>

#define B_   4
#define C_   256
#define H_   32
#define W_   32
#define N_   1024
#define NH_  8
#define HC_  32
#define NG_  4
#define GC_  64
#define BG_  16
#define SCALE_ 0.17677669529663687f   /* 32^-0.5 */
#define EPS_  1e-5f

// ---- scratch (device globals; no allocations allowed) ----
__device__ float g_q  [B_*C_*N_];
__device__ float g_pos[BG_*N_*2];
__device__ float g_xs [B_*C_*N_];
__device__ float g_k  [B_*C_*N_];
__device__ float g_v  [B_*C_*N_];
__device__ float g_o  [B_*C_*N_];

typedef unsigned long long ull;

// ---- packed f32x2 helpers ----
__device__ __forceinline__ void fma2(ull& d, ull a, ull b) {
    asm("fma.rn.f32x2 %0, %1, %2, %0;" : "+l"(d) : "l"(a), "l"(b));
}
__device__ __forceinline__ void mul2(ull& d, ull a) {
    asm("mul.rn.f32x2 %0, %0, %1;" : "+l"(d) : "l"(a));
}
__device__ __forceinline__ float2 u2f(ull v) {
    float2 r; asm("mov.b64 {%0, %1}, %2;" : "=f"(r.x), "=f"(r.y) : "l"(v)); return r;
}
__device__ __forceinline__ ull fdup(float x) {
    ull r; asm("mov.b64 %0, {%1, %1};" : "=l"(r) : "f"(x)); return r;
}

// Fast exp on the FMA pipe (avoids MUFU throughput wall).
__device__ __forceinline__ float fexp(float x) {
    float t = fmaxf(x * 1.4426950408889634f, -126.0f);
    float n = rintf(t);
    float f = t - n;
    float p =             1.3333558146e-3f;
    p = fmaf(p, f, 9.6181291794e-3f);
    p = fmaf(p, f, 5.5504108625e-2f);
    p = fmaf(p, f, 2.4022650696e-1f);
    p = fmaf(p, f, 6.9314718056e-1f);
    p = fmaf(p, f, 1.0f);
    return p * __int_as_float(((int)n + 127) << 23);
}

// ============================================================
// Projection GEMM (R3 scalar 4x4 + register double-buffer prefetch)
// ============================================================
__device__ __forceinline__ void gemm_tile(
        const float* __restrict__ Wt, const float* __restrict__ bias,
        const float* __restrict__ Xb, float* __restrict__ Yb,
        int p0, int o0, float (*Ws)[68], float (*Xs)[68]) {
    int tid = threadIdx.x;
    int tx = tid & 15, ty = tid >> 4;
    int lc = tx << 2;
    float acc[4][4] = {};
    const float* wp = Wt + (size_t)(o0 + lc) * C_ + ty;

    float w0 = wp[0], w1 = wp[C_], w2 = wp[2 * C_], w3 = wp[3 * C_];
    float4 x4 = *(const float4*)&Xb[(size_t)ty * N_ + p0 + lc];

    for (int kt = 0; kt < C_; kt += 16) {
        Ws[ty][lc + 0] = w0; Ws[ty][lc + 1] = w1;
        Ws[ty][lc + 2] = w2; Ws[ty][lc + 3] = w3;
        *(float4*)&Xs[ty][lc] = x4;
        __syncthreads();
        int nk = kt + 16;
        if (nk < C_) {
            w0 = wp[nk]; w1 = wp[C_ + nk]; w2 = wp[2 * C_ + nk]; w3 = wp[3 * C_ + nk];
            x4 = *(const float4*)&Xb[(size_t)(nk + ty) * N_ + p0 + lc];
        }
#pragma unroll
        for (int kk = 0; kk < 16; kk++) {
            float4 wv = *(const float4*)&Ws[kk][ty << 2];
            float4 xv = *(const float4*)&Xs[kk][tx << 2];
            acc[0][0] = fmaf(wv.x, xv.x, acc[0][0]);
            acc[0][1] = fmaf(wv.x, xv.y, acc[0][1]);
            acc[0][2] = fmaf(wv.x, xv.z, acc[0][2]);
            acc[0][3] = fmaf(wv.x, xv.w, acc[0][3]);
            acc[1][0] = fmaf(wv.y, xv.x, acc[1][0]);
            acc[1][1] = fmaf(wv.y, xv.y, acc[1][1]);
            acc[1][2] = fmaf(wv.y, xv.z, acc[1][2]);
            acc[1][3] = fmaf(wv.y, xv.w, acc[1][3]);
            acc[2][0] = fmaf(wv.z, xv.x, acc[2][0]);
            acc[2][1] = fmaf(wv.z, xv.y, acc[2][1]);
            acc[2][2] = fmaf(wv.z, xv.z, acc[2][2]);
            acc[2][3] = fmaf(wv.z, xv.w, acc[2][3]);
            acc[3][0] = fmaf(wv.w, xv.x, acc[3][0]);
            acc[3][1] = fmaf(wv.w, xv.y, acc[3][1]);
            acc[3][2] = fmaf(wv.w, xv.z, acc[3][2]);
            acc[3][3] = fmaf(wv.w, xv.w, acc[3][3]);
        }
        __syncthreads();
    }
#pragma unroll
    for (int i = 0; i < 4; i++) {
        int o = o0 + (ty << 2) + i;
        float bs = bias[o];
        float4 r = make_float4(acc[i][0] + bs, acc[i][1] + bs,
                               acc[i][2] + bs, acc[i][3] + bs);
        *(float4*)&Yb[(size_t)o * N_ + p0 + lc] = r;
    }
}

__global__ __launch_bounds__(256) void gemm_proj(
        const float* __restrict__ Wt, const float* __restrict__ bias,
        const float* __restrict__ X, float* __restrict__ Y) {
    __shared__ float Ws[16][68], Xs[16][68];
    int b = blockIdx.z;
    gemm_tile(Wt, bias, X + (size_t)b * C_ * N_, Y + (size_t)b * C_ * N_,
              blockIdx.x << 6, blockIdx.y << 6, Ws, Xs);
}

__global__ __launch_bounds__(256) void gemm_kv(
        const float* __restrict__ Wk, const float* __restrict__ bk,
        const float* __restrict__ Wv, const float* __restrict__ bv,
        const float* __restrict__ X, float* __restrict__ Yk, float* __restrict__ Yv) {
    __shared__ float Ws[16][68], Xs[16][68];
    int z = blockIdx.z;
    int b = z >> 1, sel = z & 1;
    gemm_tile(sel ? Wv : Wk, sel ? bv : bk,
              X + (size_t)b * C_ * N_, (sel ? Yv : Yk) + (size_t)b * C_ * N_,
              blockIdx.x << 6, blockIdx.y << 6, Ws, Xs);
}

// ============================================================
// Offset network: depthwise 3x3 -> LN -> GELU -> pointwise(2)
// ============================================================
__global__ void offset_kernel(const float* __restrict__ dw_w, const float* __restrict__ dw_b,
                              const float* __restrict__ ln_w, const float* __restrict__ ln_b,
                              const float* __restrict__ pw_w) {
    int idx = blockIdx.x * blockDim.x + threadIdx.x;   // bg*N + p
    if (idx >= BG_ * N_) return;
    int bg = idx >> 10, p = idx & (N_ - 1);
    int h = p >> 5, w = p & 31;
    int b = bg >> 2, g = bg & 3;
    const float* qbase = g_q + (size_t)b * C_ * N_ + (size_t)g * GC_ * N_;

    float x[GC_];
    float s1 = 0.f;
#pragma unroll
    for (int c = 0; c < GC_; c++) {
        const float* qc = qbase + c * N_;
        float t = dw_b[c];
#pragma unroll
        for (int dy = 0; dy < 3; dy++) {
            int hh = h + dy - 1;
            if (hh < 0 || hh >= H_) continue;
#pragma unroll
            for (int dx = 0; dx < 3; dx++) {
                int ww = w + dx - 1;
                if (ww < 0 || ww >= W_) continue;
                t += dw_w[c * 9 + dy * 3 + dx] * qc[hh * W_ + ww];
            }
        }
        x[c] = t; s1 += t;
    }
    float mu = s1 * (1.f / GC_);
    float s2 = 0.f;
#pragma unroll
    for (int c = 0; c < GC_; c++) { float d = x[c] - mu; s2 += d * d; }
    float rinv = rsqrtf(s2 * (1.f / GC_) + EPS_);
    float off0 = 0.f, off1 = 0.f;
#pragma unroll
    for (int c = 0; c < GC_; c++) {
        float xn  = (x[c] - mu) * rinv * ln_w[c] + ln_b[c];
        float gel = 0.5f * xn * (1.f + erff(xn * 0.7071067811865476f));
        off0 += pw_w[c] * gel;          // y
        off1 += pw_w[GC_ + c] * gel;    // x
    }
    const float rng = 4.0f / 31.0f;
    float py = tanhf(off0) * rng + ((0.5f + (float)h) / 31.f) * 2.f - 1.f;
    float px = tanhf(off1) * rng + ((0.5f + (float)w) / 31.f) * 2.f - 1.f;
    g_pos[idx * 2 + 0] = py;
    g_pos[idx * 2 + 1] = px;
}

// ============================================================
// Deformable bilinear sampling of kv features
// ============================================================
__global__ void sample_kernel(const float* __restrict__ kv) {
    int blk = blockIdx.x;                 // bg*N + p
    int c = threadIdx.x;
    int bg = blk >> 10, p = blk & (N_ - 1);
    int b = bg >> 2, g = bg & 3;
    float py = g_pos[blk * 2 + 0], px = g_pos[blk * 2 + 1];
    float ix = (px + 1.f) * 15.5f;
    float iy = (py + 1.f) * 15.5f;
    float x0f = floorf(ix), y0f = floorf(iy);
    float wx1 = ix - x0f, wx0 = 1.f - wx1;
    float wy1 = iy - y0f, wy0 = 1.f - wy1;
    int x0 = (int)x0f, y0 = (int)y0f;
    const float* src = kv + ((size_t)b * C_ + g * GC_ + c) * N_;
    float acc = 0.f;
#pragma unroll
    for (int cy = 0; cy < 2; cy++) {
        int yy = y0 + cy;
        if (yy < 0 || yy >= H_) continue;
        float wy = cy ? wy1 : wy0;
#pragma unroll
        for (int cx = 0; cx < 2; cx++) {
            int xx = x0 + cx;
            if (xx < 0 || xx >= W_) continue;
            acc += wy * (cx ? wx1 : wx0) * src[yy * W_ + xx];
        }
    }
    g_xs[((size_t)b * C_ + g * GC_ + c) * N_ + p] = acc;
}

// ============================================================
// Fused flash attention.
// QK: FFMA2 packed over m (q naturally paired; k dup'd in regs).
// PV: FFMA2 packed over n (both operands naturally paired).
// Online softmax WITH max subtraction; per-thread partial sums.
// RPE bias: fp32 69x69 zero-padded smem table (pad 3 each side;
// coordinate range y0 in [-3,64]), constant-fraction bilinear.
// ============================================================
#define FL_QS 0
#define FL_KS 8704
#define FL_VS 17408
#define FL_PS 26112
#define FL_TB 43520            /* 69*69 floats = 19044 B (pad to 19072) */
#define FL_PY 62592
#define FL_PX 62848
#define FL_SMEM 63104

__global__ __launch_bounds__(256) void flash_kernel(const float* __restrict__ rpe) {
    extern __shared__ char sm_[];
    float* qs  = (float*)(sm_ + FL_QS);    // [32][68]  (pre-scaled q)
    float* ks  = (float*)(sm_ + FL_KS);    // [32][68]
    float* vs  = (float*)(sm_ + FL_VS);    // [32][68]
    float* ps  = (float*)(sm_ + FL_PS);    // [64][68]
    float* tb  = (float*)(sm_ + FL_TB);    // [69][69] zero-padded
    float* pyn = (float*)(sm_ + FL_PY);    // 64
    float* pxn = (float*)(sm_ + FL_PX);    // 64

    int tid = threadIdx.x;
    int tx = tid & 15, ty = tid >> 4;
    int bh = blockIdx.y, b = bh >> 3, hd = bh & 7;
    int m0 = blockIdx.x << 6;

    const float* qb = g_q + (size_t)(b * C_ + hd * HC_) * N_;
    const float* kb = g_k + (size_t)(b * C_ + hd * HC_) * N_;
    const float* vb = g_v + (size_t)(b * C_ + hd * HC_) * N_;
    int bg = b * NG_ + (hd >> 1);
    const float* tsrc = rpe + hd * 3969;

    // zero padded table, load q tile (scaled)
    for (int i = tid; i < 69 * 69; i += 256) tb[i] = 0.f;
    for (int i = tid; i < 512; i += 256) {
        int c = i >> 4, col = (i & 15) << 2;
        float4 v = *(const float4*)&qb[(size_t)c * N_ + m0 + col];
        v.x *= SCALE_; v.y *= SCALE_; v.z *= SCALE_; v.w *= SCALE_;
        *(float4*)&qs[c * 68 + col] = v;
    }
    __syncthreads();
    // table interior at [3][3]
    for (int i = tid; i < 3969; i += 256) {
        int y = i / 63, x = i - y * 63;
        tb[(y + 3) * 69 + x + 3] = tsrc[i];
    }

    int moff[4];
#pragma unroll
    for (int i = 0; i < 4; i++) {
        int m = m0 + (ty << 2) + i;
        moff[i] = (m >> 5) * 69 + (m & 31);
    }

    float runm[4] = {-1e30f, -1e30f, -1e30f, -1e30f};
    float rsum[4] = {};
    ull o20[4] = {}, o21[4] = {};   // packed n-pair partials, channels tx / tx+16

    for (int nt = 0; nt < 16; nt++) {
        int n0 = nt << 6;
        __syncthreads();   // prev PV done (iter 0: table fill done)
        for (int i = tid; i < 512; i += 256) {
            int c = i >> 4, col = (i & 15) << 2;
            *(float4*)&ks[c * 68 + col] = *(const float4*)&kb[(size_t)c * N_ + n0 + col];
            *(float4*)&vs[c * 68 + col] = *(const float4*)&vb[(size_t)c * N_ + n0 + col];
        }
        if (tid < 64) {
            pyn[tid] = 15.5f - 15.5f * g_pos[((size_t)bg * N_ + n0 + tid) * 2 + 0];
            pxn[tid] = 15.5f - 15.5f * g_pos[((size_t)bg * N_ + n0 + tid) * 2 + 1];
        }
        __syncthreads();

        // ---- S = Q^T K: FFMA2 packed over m ----
        // acc2[j][p]: j = n-idx 0..3, p = m-pair (m0,m1)/(m2,m3)
        ull acc2[4][2] = {};
#pragma unroll
        for (int c = 0; c < 32; c++) {
            ulonglong2 qp = *(const ulonglong2*)&qs[c * 68 + (ty << 2)];
            float4 kv4 = *(const float4*)&ks[c * 68 + (tx << 2)];
            ull kd0 = fdup(kv4.x), kd1 = fdup(kv4.y);
            ull kd2 = fdup(kv4.z), kd3 = fdup(kv4.w);
            fma2(acc2[0][0], kd0, qp.x); fma2(acc2[0][1], kd0, qp.y);
            fma2(acc2[1][0], kd1, qp.x); fma2(acc2[1][1], kd1, qp.y);
            fma2(acc2[2][0], kd2, qp.x); fma2(acc2[2][1], kd2, qp.y);
            fma2(acc2[3][0], kd3, qp.x); fma2(acc2[3][1], kd3, qp.y);
        }
        float sv[4][4];
#pragma unroll
        for (int j = 0; j < 4; j++) {
            float2 a = u2f(acc2[j][0]), c2 = u2f(acc2[j][1]);
            sv[0][j] = a.x; sv[1][j] = a.y; sv[2][j] = c2.x; sv[3][j] = c2.y;
        }

        // ---- + rpe bias (fractions constant per n; pad-3 table) ----
#pragma unroll
        for (int j = 0; j < 4; j++) {
            int nn = (tx << 2) + j;
            float biy = pyn[nn], bix = pxn[nn];
            float fy = floorf(biy), fx = floorf(bix);
            float wy1 = biy - fy, wx1 = bix - fx;
            float wy0 = 1.f - wy1, wx0 = 1.f - wx1;
            int idxb = ((int)fy + 3) * 69 + (int)fx + 3;
            float w00 = wy0 * wx0, w01 = wy0 * wx1;
            float w10 = wy1 * wx0, w11 = wy1 * wx1;
#pragma unroll
            for (int i = 0; i < 4; i++) {
                int idx = idxb + moff[i];
                sv[i][j] += w00 * tb[idx] + w01 * tb[idx + 1]
                          + w10 * tb[idx + 69] + w11 * tb[idx + 70];
            }
        }

        // ---- online softmax: max via shfl; sums stay per-thread ----
#pragma unroll
        for (int i = 0; i < 4; i++) {
            float tm = fmaxf(fmaxf(sv[i][0], sv[i][1]), fmaxf(sv[i][2], sv[i][3]));
#pragma unroll
            for (int off = 1; off < 16; off <<= 1)
                tm = fmaxf(tm, __shfl_xor_sync(0xffffffffu, tm, off));
            float nm = fmaxf(runm[i], tm);
            float corr = fexp(runm[i] - nm);
            runm[i] = nm;
            float p0 = fexp(sv[i][0] - nm);
            float p1 = fexp(sv[i][1] - nm);
            float p2 = fexp(sv[i][2] - nm);
            float p3 = fexp(sv[i][3] - nm);
            rsum[i] = rsum[i] * corr + ((p0 + p1) + (p2 + p3));
            ull cd = fdup(corr);
            mul2(o20[i], cd); mul2(o21[i], cd);
            *(float4*)&ps[((ty << 2) + i) * 68 + (tx << 2)] = make_float4(p0, p1, p2, p3);
        }
        __syncwarp();

        // ---- O += P V: FFMA2 packed over n ----
#pragma unroll
        for (int n4 = 0; n4 < 16; n4++) {
            ulonglong2 v0 = *(const ulonglong2*)&vs[tx * 68 + (n4 << 2)];
            ulonglong2 v1 = *(const ulonglong2*)&vs[(tx + 16) * 68 + (n4 << 2)];
#pragma unroll
            for (int i = 0; i < 4; i++) {
                ulonglong2 pp = *(const ulonglong2*)&ps[((ty << 2) + i) * 68 + (n4 << 2)];
                fma2(o20[i], pp.x, v0.x); fma2(o20[i], pp.y, v0.y);
                fma2(o21[i], pp.x, v1.x); fma2(o21[i], pp.y, v1.y);
            }
        }
    }

    // final row-sum reduction (once) and normalize
    float inv[4];
#pragma unroll
    for (int i = 0; i < 4; i++) {
        float rs = rsum[i];
#pragma unroll
        for (int off = 1; off < 16; off <<= 1)
            rs += __shfl_xor_sync(0xffffffffu, rs, off);
        inv[i] = 1.f / rs;
    }
    __syncthreads();
#pragma unroll
    for (int i = 0; i < 4; i++) {
        float2 a = u2f(o20[i]), c2 = u2f(o21[i]);
        ps[((ty << 2) + i) * 68 + tx]      = (a.x + a.y) * inv[i];
        ps[((ty << 2) + i) * 68 + tx + 16] = (c2.x + c2.y) * inv[i];
    }
    __syncthreads();
    float* ob = g_o + (size_t)(b * C_ + hd * HC_) * N_;
    for (int i = tid; i < 2048; i += 256) {
        int c = i >> 6, m = i & 63;
        ob[(size_t)c * N_ + m0 + m] = ps[m * 68 + c];
    }
}

// ============================================================
extern "C" void kernel_launch(void* const* d_in, const int* in_sizes, int n_in,
                              void* d_out, int out_size) {
    const float* q_feat = (const float*)d_in[0];
    const float* kv_feat = (const float*)d_in[1];
    const float* Wq = (const float*)d_in[2];
    const float* bq = (const float*)d_in[3];
    const float* Wk = (const float*)d_in[4];
    const float* bk = (const float*)d_in[5];
    const float* Wv = (const float*)d_in[6];
    const float* bv = (const float*)d_in[7];
    const float* Wo = (const float*)d_in[8];
    const float* bo = (const float*)d_in[9];
    const float* dw_w = (const float*)d_in[10];
    const float* dw_b = (const float*)d_in[11];
    const float* ln_w = (const float*)d_in[12];
    const float* ln_b = (const float*)d_in[13];
    const float* pw_w = (const float*)d_in[14];
    const float* rpe  = (const float*)d_in[15];
    float* out = (float*)d_out;

    float *gq, *gxs, *gk, *gv, *go;
    cudaGetSymbolAddress((void**)&gq,  g_q);
    cudaGetSymbolAddress((void**)&gxs, g_xs);
    cudaGetSymbolAddress((void**)&gk,  g_k);
    cudaGetSymbolAddress((void**)&gv,  g_v);
    cudaGetSymbolAddress((void**)&go,  g_o);

    static int smem_set = 0;
    if (!smem_set) {
        cudaFuncSetAttribute(flash_kernel,
                             cudaFuncAttributeMaxDynamicSharedMemorySize, FL_SMEM);
        smem_set = 1;
    }

    dim3 gemm_grid(N_ / 64, C_ / 64, B_);
    dim3 kv_grid(N_ / 64, C_ / 64, B_ * 2);

    gemm_proj<<<gemm_grid, 256>>>(Wq, bq, q_feat, gq);
    offset_kernel<<<(BG_ * N_ + 255) / 256, 256>>>(dw_w, dw_b, ln_w, ln_b, pw_w);
    sample_kernel<<<BG_ * N_, GC_>>>(kv_feat);
    gemm_kv<<<kv_grid, 256>>>(Wk, bk, Wv, bv, gxs, gk, gv);
    flash_kernel<<<dim3(N_ / 64, B_ * NH_), 256, FL_SMEM>>>(rpe);
    gemm_proj<<<gemm_grid, 256>>>(Wo, bo, go, out);
}